// round 1
// baseline (speedup 1.0000x reference)
#include <cuda_runtime.h>
#include <cuda_bf16.h>
#include <math.h>

#define B_ 2
#define S_ 4096
#define D_ 512
#define H_ 8
#define DK_ 64
#define MROWS (B_ * S_)   // 8192

// ---------------- scratch (no allocations allowed) ----------------
__device__ float g_Q[MROWS * D_];
__device__ float g_K[MROWS * D_];
__device__ float g_V[MROWS * D_];
__device__ float g_AO[MROWS * D_];

// ---------------- GEMM: C[M,512] = A[M,512] @ W[512,512]^T ----------------
// 64x64 block tile, 256 threads, 4x4 microtile, BK=16
#define GBM 64
#define GBN 64
#define GBK 16

__device__ __forceinline__ void gemm_tile(const float* __restrict__ A,
                                          const float* __restrict__ W,
                                          float* __restrict__ C) {
    __shared__ float As[GBM][GBK + 1];
    __shared__ float Ws[GBN][GBK + 1];

    const int tid = threadIdx.x;
    const int tx = tid & 15;
    const int ty = tid >> 4;
    const int m0 = blockIdx.x * GBM;
    const int n0 = blockIdx.y * GBN;

    float acc[4][4] = {};

    for (int k0 = 0; k0 < D_; k0 += GBK) {
#pragma unroll
        for (int i = 0; i < 4; i++) {
            int e = tid + i * 256;
            int r = e >> 4, c = e & 15;
            As[r][c] = A[(m0 + r) * D_ + k0 + c];
            Ws[r][c] = W[(n0 + r) * D_ + k0 + c];
        }
        __syncthreads();
#pragma unroll
        for (int k = 0; k < GBK; k++) {
            float a[4], w[4];
#pragma unroll
            for (int r = 0; r < 4; r++) a[r] = As[ty * 4 + r][k];
#pragma unroll
            for (int c = 0; c < 4; c++) w[c] = Ws[tx * 4 + c][k];
#pragma unroll
            for (int r = 0; r < 4; r++)
#pragma unroll
                for (int c = 0; c < 4; c++) acc[r][c] += a[r] * w[c];
        }
        __syncthreads();
    }

#pragma unroll
    for (int r = 0; r < 4; r++)
#pragma unroll
        for (int c = 0; c < 4; c++)
            C[(m0 + ty * 4 + r) * D_ + n0 + tx * 4 + c] = acc[r][c];
}

// Fused Q/K/V projection: blockIdx.z selects which projection.
__global__ void proj_qkv_kernel(const float* __restrict__ q,
                                const float* __restrict__ k,
                                const float* __restrict__ v,
                                const float* __restrict__ wq,
                                const float* __restrict__ wk,
                                const float* __restrict__ wv) {
    int z = blockIdx.z;
    const float* A = (z == 0) ? q : (z == 1) ? k : v;
    const float* W = (z == 0) ? wq : (z == 1) ? wk : wv;
    float* C = (z == 0) ? g_Q : (z == 1) ? g_K : g_V;
    gemm_tile(A, W, C);
}

__global__ void proj_out_kernel(const float* __restrict__ wo,
                                float* __restrict__ out) {
    gemm_tile(g_AO, wo, out);
}

// ---------------- Flash attention (fp32, online softmax) ----------------
// grid: (S/64, B*H), block: 256 threads (16x16), 64x64 q/k tiles.
// Dynamic smem layout:
//   Qs[64][64]      (4096 f)
//   KsPs[64][65]    (4160 f)  K tile, reused as P tile
//   Vs[64][64]      (4096 f)
//   msk[64]         (64 i)
#define FSM_FLOATS (4096 + 4160 + 4096)
#define FSM_BYTES  (FSM_FLOATS * 4 + 64 * 4)

__global__ void flash_attn_kernel(const int* __restrict__ mask) {
    extern __shared__ float sm[];
    float* Qs = sm;                 // stride 64
    float* KsPs = sm + 4096;        // stride 65
    float* Vs = sm + 4096 + 4160;   // stride 64
    int* msk = (int*)(sm + FSM_FLOATS);

    const int tid = threadIdx.x;
    const int tx = tid & 15;
    const int ty = tid >> 4;
    const int bh = blockIdx.y;
    const int b = bh >> 3;
    const int h = bh & 7;
    const int qm0 = blockIdx.x * 64;
    const float scale = 0.125f;  // 1/sqrt(64)

    const float* Qb = g_Q + (b * S_ + qm0) * D_ + h * DK_;

    // load Q tile (64x64)
#pragma unroll
    for (int i = 0; i < 16; i++) {
        int e = tid + i * 256;
        int r = e >> 6, c = e & 63;
        Qs[r * 64 + c] = Qb[r * D_ + c];
    }

    float m_r[4], l_r[4], o[4][4] = {};
#pragma unroll
    for (int r = 0; r < 4; r++) { m_r[r] = -1e30f; l_r[r] = 0.0f; }

    for (int kn0 = 0; kn0 < S_; kn0 += 64) {
        const float* Kb = g_K + (b * S_ + kn0) * D_ + h * DK_;
        const float* Vb = g_V + (b * S_ + kn0) * D_ + h * DK_;

        __syncthreads();  // previous iteration's readers of KsPs/Vs done
#pragma unroll
        for (int i = 0; i < 16; i++) {
            int e = tid + i * 256;
            int r = e >> 6, c = e & 63;
            KsPs[r * 65 + c] = Kb[r * D_ + c];
            Vs[r * 64 + c] = Vb[r * D_ + c];
        }
        if (tid < 64) msk[tid] = mask[b * S_ + kn0 + tid];
        __syncthreads();

        // scores S = Q K^T  (4x4 per thread)
        float s[4][4] = {};
#pragma unroll 4
        for (int d = 0; d < 64; d++) {
            float a[4], kk[4];
#pragma unroll
            for (int r = 0; r < 4; r++) a[r] = Qs[(ty * 4 + r) * 64 + d];
#pragma unroll
            for (int c = 0; c < 4; c++) kk[c] = KsPs[(tx * 4 + c) * 65 + d];
#pragma unroll
            for (int r = 0; r < 4; r++)
#pragma unroll
                for (int c = 0; c < 4; c++) s[r][c] += a[r] * kk[c];
        }

        int mk[4];
#pragma unroll
        for (int c = 0; c < 4; c++) mk[c] = msk[tx * 4 + c];
#pragma unroll
        for (int r = 0; r < 4; r++)
#pragma unroll
            for (int c = 0; c < 4; c++)
                s[r][c] = mk[c] ? s[r][c] * scale : -1e30f;

        // row max across the 16 tx lanes
        float mnew[4], alpha[4];
#pragma unroll
        for (int r = 0; r < 4; r++) {
            float tm = fmaxf(fmaxf(s[r][0], s[r][1]), fmaxf(s[r][2], s[r][3]));
#pragma unroll
            for (int off = 1; off < 16; off <<= 1)
                tm = fmaxf(tm, __shfl_xor_sync(0xffffffffu, tm, off));
            mnew[r] = fmaxf(m_r[r], tm);
            alpha[r] = __expf(m_r[r] - mnew[r]);
            m_r[r] = mnew[r];
        }

        __syncthreads();  // everyone done reading K from KsPs

        // P = exp(S - m), write into KsPs (reused), accumulate row sums
        float rs[4] = {};
#pragma unroll
        for (int r = 0; r < 4; r++) {
#pragma unroll
            for (int c = 0; c < 4; c++) {
                float p = mk[c] ? __expf(s[r][c] - mnew[r]) : 0.0f;
                KsPs[(ty * 4 + r) * 65 + tx * 4 + c] = p;
                rs[r] += p;
            }
        }
#pragma unroll
        for (int r = 0; r < 4; r++) {
#pragma unroll
            for (int off = 1; off < 16; off <<= 1)
                rs[r] += __shfl_xor_sync(0xffffffffu, rs[r], off);
            l_r[r] = l_r[r] * alpha[r] + rs[r];
#pragma unroll
            for (int c = 0; c < 4; c++) o[r][c] *= alpha[r];
        }

        __syncthreads();  // P tile complete

        // O += P @ V
#pragma unroll 4
        for (int j = 0; j < 64; j++) {
            float p[4], v[4];
#pragma unroll
            for (int r = 0; r < 4; r++) p[r] = KsPs[(ty * 4 + r) * 65 + j];
#pragma unroll
            for (int c = 0; c < 4; c++) v[c] = Vs[j * 64 + tx * 4 + c];
#pragma unroll
            for (int r = 0; r < 4; r++)
#pragma unroll
                for (int c = 0; c < 4; c++) o[r][c] += p[r] * v[c];
        }
    }

    // normalize and write (fully-masked rows -> 0, matching nan_to_num)
    float* Ob = g_AO + (b * S_ + qm0) * D_ + h * DK_;
#pragma unroll
    for (int r = 0; r < 4; r++) {
        float inv = (l_r[r] > 0.0f) ? (1.0f / l_r[r]) : 0.0f;
#pragma unroll
        for (int c = 0; c < 4; c++)
            Ob[(ty * 4 + r) * D_ + tx * 4 + c] = o[r][c] * inv;
    }
}

// ---------------- launch ----------------
extern "C" void kernel_launch(void* const* d_in, const int* in_sizes, int n_in,
                              void* d_out, int out_size) {
    const float* q  = (const float*)d_in[0];
    const float* k  = (const float*)d_in[1];
    const float* v  = (const float*)d_in[2];
    const int* mask = (const int*)d_in[3];
    const float* wq = (const float*)d_in[4];
    const float* wk = (const float*)d_in[5];
    const float* wv = (const float*)d_in[6];
    const float* wo = (const float*)d_in[7];
    float* out = (float*)d_out;

    // QKV projections
    dim3 gproj(MROWS / GBM, D_ / GBN, 3);
    proj_qkv_kernel<<<gproj, 256>>>(q, k, v, wq, wk, wv);

    // flash attention
    cudaFuncSetAttribute(flash_attn_kernel,
                         cudaFuncAttributeMaxDynamicSharedMemorySize, FSM_BYTES);
    dim3 gattn(S_ / 64, B_ * H_);
    flash_attn_kernel<<<gattn, 256, FSM_BYTES>>>(mask);

    // output projection
    dim3 gout(MROWS / GBM, D_ / GBN);
    proj_out_kernel<<<gout, 256>>>(wo, out);
}